// round 17
// baseline (speedup 1.0000x reference)
#include <cuda_runtime.h>

// out[b, i, f] = x[b, i] * W[i, f] + bias[i, f]
// BS=16384, DEMO_DIM=32, FEAT_DIM=256 -> 512 MiB fp32 out. Pure HBM-store-bound.
//
// Round-16: LAST cache-policy ablation — __stwt (write-through) vs __stcs.
// Cache policy is the only axis that moved perf in this family (.cs vs
// default = 3%). Theory: .wt streams sectors straight toward the memory
// controller, avoiding the L2 dirty-fill -> drain two-phase and the
// kernel-end flush tail. Counter-risk: no L2 coalescing window -> possible
// partial-line DRAM writes (the R12 plain-store failure mode).
// Everything else identical to the 74.2us record (R3/R12/R14):
//   BPT=8, 16384 CTAs x 256 threads, 32 regs, occ ~94%, interleaved
//   load->fma->store, 512B warp-coalesced stores.

#define BS        16384
#define DEMO_DIM  32
#define FEAT_DIM  256
#define F4        (FEAT_DIM / 4)                 // 64 float4 per (b,i)
#define ROW4      (DEMO_DIM * F4)                // 2048 float4 per batch
#define BPT       8                              // batches per thread
#define THREADS   256
#define OFF_CHUNKS (ROW4 / THREADS)              // 8 chunks of 256 float4 per row
#define NBLOCKS   ((BS / BPT) * OFF_CHUNKS)      // 2048 * 8 = 16384 blocks

__global__ __launch_bounds__(THREADS) void demo_proj_kernel(
    const float*  __restrict__ x,     // [BS, DEMO_DIM]
    const float4* __restrict__ W4,    // [DEMO_DIM, F4]
    const float4* __restrict__ B4,    // [DEMO_DIM, F4]
    float4*       __restrict__ out4)  // [BS, DEMO_DIM, F4]
{
    // Low 3 bits of blockIdx pick the 256-float4 chunk within the
    // 2048-float4 row; high bits pick the group of BPT batches.
    int off_chunk = blockIdx.x & (OFF_CHUNKS - 1);
    int bgroup    = blockIdx.x >> 3;

    int off = off_chunk * THREADS + threadIdx.x;   // 0..2047, fixed per thread
    int i   = off >> 6;                            // demo index, fixed
    int f4  = off & (F4 - 1);                      // feature chunk, fixed

    // Per-thread W/b loaded ONCE; reused for all BPT batches.
    float4 w  = __ldg(&W4[i * F4 + f4]);
    float4 bv = __ldg(&B4[i * F4 + f4]);

    int bb0 = bgroup * BPT;
    const float* xrow = x + bb0 * DEMO_DIM + i;
    float4* dst = out4 + (long long)bb0 * ROW4 + off;

#pragma unroll
    for (int k = 0; k < BPT; k++) {
        float xv = __ldg(xrow + k * DEMO_DIM);     // uniform per warp, L1 hit
        float4 o;
        o.x = fmaf(xv, w.x, bv.x);
        o.y = fmaf(xv, w.y, bv.y);
        o.z = fmaf(xv, w.z, bv.z);
        o.w = fmaf(xv, w.w, bv.w);
        __stwt(dst + (long long)k * ROW4, o);      // write-through streaming store
    }
}

extern "C" void kernel_launch(void* const* d_in, const int* in_sizes, int n_in,
                              void* d_out, int out_size)
{
    const float*  x  = (const float*)d_in[0];
    const float4* W4 = (const float4*)d_in[1];
    const float4* B4 = (const float4*)d_in[2];
    float4* out4 = (float4*)d_out;

    demo_proj_kernel<<<NBLOCKS, THREADS>>>(x, W4, B4, out4);
}